// round 1
// baseline (speedup 1.0000x reference)
#include <cuda_runtime.h>

#define MARGIN 0.5f
#define WARPS_PER_BLOCK 8

// Scratch accumulators (no device allocation allowed -> __device__ globals)
__device__ float        g_total;
__device__ unsigned int g_count;

__global__ void mpcl_init_kernel() {
    g_total = 0.0f;
    g_count = 0u;
}

__global__ void mpcl_finalize_kernel(float* __restrict__ out) {
    unsigned c = g_count;
    out[0] = (c > 0u) ? (g_total / (float)c) : 0.0f;
}

// One warp per problem. Lanes cooperatively hold the neg scores (2 regs cover
// N<=64); 16 lanes hold pos scores; inner loop is uniform length pc -> no
// ragged-count divergence. Invalid neg lanes are -1e30 so relu kills them
// without predication.
__global__ void __launch_bounds__(WARPS_PER_BLOCK * 32)
mpcl_main_kernel(const float* __restrict__ scores,
                 const int*   __restrict__ pos_indices,
                 const int*   __restrict__ neg_indices,
                 const int*   __restrict__ pos_counts,
                 const int*   __restrict__ neg_counts,
                 int B, int C, int P, int N)
{
    __shared__ float    s_tot[WARPS_PER_BLOCK];
    __shared__ unsigned s_cnt[WARPS_PER_BLOCK];

    const int warp = threadIdx.x >> 5;
    const int lane = threadIdx.x & 31;
    const int b    = blockIdx.x * WARPS_PER_BLOCK + warp;

    float    acc = 0.0f;
    unsigned cnt = 0u;

    if (b < B) {
        const int pc = pos_counts[b];   // broadcast load (same addr all lanes)
        const int nc = neg_counts[b];
        if (pc > 0 && nc > 0) {
            cnt = (unsigned)(pc * nc);

            const float* s  = scores      + (size_t)b * (size_t)C;
            const int*   ni = neg_indices + (size_t)b * (size_t)N;
            const int*   pi = pos_indices + (size_t)b * (size_t)P;

            // Preload negatives: lane l -> neg index l, lane l (l<16 when N=48)
            // also holds index l+32. Invalid slots get -1e30 -> relu yields 0.
            float neg0 = -1e30f;
            float neg1 = -1e30f;
            if (lane < nc)      neg0 = s[ni[lane]];
            if (lane + 32 < nc) neg1 = s[ni[lane + 32]];

            // Preload positives into lanes 0..pc-1
            float poss = 0.0f;
            if (lane < pc) poss = s[pi[lane]];

            for (int p = 0; p < pc; p++) {
                const float a  = MARGIN - __shfl_sync(0xffffffffu, poss, p);
                acc += fmaxf(a + neg0, 0.0f);
                acc += fmaxf(a + neg1, 0.0f);
            }
        }
    }

    // Warp reduction of acc
    #pragma unroll
    for (int o = 16; o > 0; o >>= 1)
        acc += __shfl_xor_sync(0xffffffffu, acc, o);

    if (lane == 0) {
        s_tot[warp] = acc;
        s_cnt[warp] = cnt;
    }
    __syncthreads();

    if (threadIdx.x == 0) {
        float    t = 0.0f;
        unsigned c = 0u;
        #pragma unroll
        for (int w = 0; w < WARPS_PER_BLOCK; w++) {
            t += s_tot[w];
            c += s_cnt[w];
        }
        atomicAdd(&g_total, t);
        atomicAdd(&g_count, c);
    }
}

extern "C" void kernel_launch(void* const* d_in, const int* in_sizes, int n_in,
                              void* d_out, int out_size)
{
    const float* scores      = (const float*)d_in[0];
    const int*   pos_indices = (const int*)  d_in[1];
    const int*   neg_indices = (const int*)  d_in[2];
    const int*   pos_counts  = (const int*)  d_in[3];
    const int*   neg_counts  = (const int*)  d_in[4];
    float*       out         = (float*)d_out;

    const int B = in_sizes[3];             // pos_counts element count
    const int C = in_sizes[0] / B;         // candidates per problem
    const int P = in_sizes[1] / B;         // max positives
    const int N = in_sizes[2] / B;         // max negatives

    mpcl_init_kernel<<<1, 1>>>();

    const int blocks = (B + WARPS_PER_BLOCK - 1) / WARPS_PER_BLOCK;
    mpcl_main_kernel<<<blocks, WARPS_PER_BLOCK * 32>>>(
        scores, pos_indices, neg_indices, pos_counts, neg_counts, B, C, P, N);

    mpcl_finalize_kernel<<<1, 1>>>(out);
}